// round 14
// baseline (speedup 1.0000x reference)
#include <cuda_runtime.h>
#include <math.h>

#define NODES 20000

typedef unsigned long long ull;

__device__ float g_qkt[(size_t)NODES * 512];
__device__ float g_u[(size_t)NODES * 512];
__device__ float g_wkt[128 * 128];   // WkT[c][g] = Wk[g][c]
__device__ float g_w2[512 * 128];    // fused blockdiag(Wv)@Wo
__device__ float g_b2[128];          // bv@Wo + bo

__device__ __forceinline__ ull pk2(float x) {
    unsigned xi = __float_as_uint(x);
    ull r;
    asm("mov.b64 %0, {%1, %1};" : "=l"(r) : "r"(xi), "r"(xi));
    return r;
}
__device__ __forceinline__ ull ffma2(ull a, ull b, ull c) {
    ull d;
    asm("fma.rn.f32x2 %0, %1, %2, %3;" : "=l"(d) : "l"(a), "l"(b), "l"(c));
    return d;
}
__device__ __forceinline__ void upk(ull v, float& lo, float& hi) {
    unsigned a, b;
    asm("mov.b64 {%0, %1}, %2;" : "=r"(a), "=r"(b) : "l"(v));
    lo = __uint_as_float(a); hi = __uint_as_float(b);
}

// 8 rows x 4 cols over 4 k: A from smem (warp-private rows, broadcast reads),
// B via 16B-per-lane loads from gB (global, coalesced 512B rows, L1-hot).
#define GEMM_STEP_LDGB(bA, kbase, gB, kg, c0, acc)                                     \
    {                                                                                   \
        ulonglong2 b0 = *(const ulonglong2*)((gB) + ((kg) + 0) * 128 + (c0));           \
        ulonglong2 b1 = *(const ulonglong2*)((gB) + ((kg) + 1) * 128 + (c0));           \
        ulonglong2 b2 = *(const ulonglong2*)((gB) + ((kg) + 2) * 128 + (c0));           \
        ulonglong2 b3 = *(const ulonglong2*)((gB) + ((kg) + 3) * 128 + (c0));           \
        _Pragma("unroll")                                                               \
        for (int i = 0; i < 8; i++) {                                                   \
            float4 a = *(const float4*)((bA) + i * 132 + (kbase));                      \
            ull A;                                                                      \
            A = pk2(a.x); acc[i][0] = ffma2(A, b0.x, acc[i][0]); acc[i][1] = ffma2(A, b0.y, acc[i][1]); \
            A = pk2(a.y); acc[i][0] = ffma2(A, b1.x, acc[i][0]); acc[i][1] = ffma2(A, b1.y, acc[i][1]); \
            A = pk2(a.z); acc[i][0] = ffma2(A, b2.x, acc[i][0]); acc[i][1] = ffma2(A, b2.y, acc[i][1]); \
            A = pk2(a.w); acc[i][0] = ffma2(A, b3.x, acc[i][0]); acc[i][1] = ffma2(A, b3.y, acc[i][1]); \
        }                                                                               \
    }

// ---------------------------------------------------------------------------
// K0: WkT transpose (one-shot, 64KB)
// ---------------------------------------------------------------------------
__global__ __launch_bounds__(256) void k0_transpose(const float* __restrict__ Wk)
{
    __shared__ float tile[32][33];
    const int bx = blockIdx.x & 3, by = blockIdx.x >> 2;
    const int x = threadIdx.x & 31, y = threadIdx.x >> 5;  // 32 x 8
#pragma unroll
    for (int i = 0; i < 32; i += 8)
        tile[y + i][x] = Wk[(by * 32 + y + i) * 128 + bx * 32 + x];
    __syncthreads();
#pragma unroll
    for (int i = 0; i < 32; i += 8)
        g_wkt[(bx * 32 + y + i) * 128 + by * 32 + x] = tile[x][y + i];
}

// ---------------------------------------------------------------------------
// K0b: W2 = blockdiag(Wv) @ Wo  (512x128), b2 = bv @ Wo + bo  (one-shot)
// ---------------------------------------------------------------------------
__global__ __launch_bounds__(256) void k0b_fuse(
    const float* __restrict__ Wv, const float* __restrict__ Wo,
    const float* __restrict__ bv, const float* __restrict__ bo)
{
    const int gid = blockIdx.x * 256 + threadIdx.x;   // 0..65535
    const int k = gid >> 7, c = gid & 127;
    const int h = k >> 7, f = k & 127;
    float s = 0.f;
#pragma unroll
    for (int d = 0; d < 32; d++)
        s += Wv[f * 128 + h * 32 + d] * Wo[(h * 32 + d) * 128 + c];
    g_w2[k * 128 + c] = s;
    if (gid < 128) {
        float b = bo[gid];
#pragma unroll 4
        for (int dd = 0; dd < 128; dd++) b += bv[dd] * Wo[dd * 128 + gid];
        g_b2[gid] = b;
    }
}

// ---------------------------------------------------------------------------
// K1: q = query@Wq + bq;  qkt[n,h,g] = scale * sum_d q[h,d] * WkT[h*32+d][g]
// 64 nodes/CTA, warp-private 8 rows. NO __syncthreads. Weights via LDG.
// ---------------------------------------------------------------------------
__global__ __launch_bounds__(256, 3) void k1_kernel(
    const float* __restrict__ query, const float* __restrict__ Wq,
    const float* __restrict__ bq)
{
    __shared__ float bufQ[64 * 132];

    const int t = threadIdx.x;
    const int n0 = blockIdx.x * 64;
    const int lane = t & 31, wg = t >> 5;
    const int c0 = 4 * lane, r0 = 8 * wg;
    float* myA = bufQ + r0 * 132;   // warp-private 8 rows

    // load this warp's 8 query rows into smem (coalesced 512B per row)
#pragma unroll
    for (int i = 0; i < 8; i++) {
        const int row = n0 + r0 + i;
        float4 v = (row < NODES) ? *(const float4*)(query + (size_t)row * 128 + c0)
                                 : make_float4(0.f, 0.f, 0.f, 0.f);
        *(float4*)(myA + i * 132 + c0) = v;
    }
    __syncwarp();

    // stage A: Q = A @ Wq + bq  (Wq streamed via LDG, L1-hot)
    ull acc[8][2];
#pragma unroll
    for (int i = 0; i < 8; i++) { acc[i][0] = 0ull; acc[i][1] = 0ull; }
#pragma unroll 4
    for (int k = 0; k < 128; k += 4) {
        GEMM_STEP_LDGB(myA, k, Wq, k, c0, acc);
    }
    __syncwarp();   // all stage-A reads of myA done before overwrite

    {
        float4 b4 = *(const float4*)(bq + c0);
#pragma unroll
        for (int i = 0; i < 8; i++) {
            float lo0, hi0, lo1, hi1;
            upk(acc[i][0], lo0, hi0); upk(acc[i][1], lo1, hi1);
            *(float4*)(myA + i * 132 + c0) =
                make_float4(lo0 + b4.x, hi0 + b4.y, lo1 + b4.z, hi1 + b4.w);
        }
    }
    __syncwarp();

    // stage B: per-head qkt (WkT via LDG)
    const float scale = 0.17677669529663688f;  // 1/sqrt(32)
#pragma unroll
    for (int h = 0; h < 4; h++) {
        ull a2[8][2];
#pragma unroll
        for (int i = 0; i < 8; i++) { a2[i][0] = 0ull; a2[i][1] = 0ull; }
#pragma unroll 4
        for (int d = 0; d < 32; d += 4) {
            GEMM_STEP_LDGB(myA, h * 32 + d, g_wkt, h * 32 + d, c0, a2);
        }
#pragma unroll
        for (int i = 0; i < 8; i++) {
            if (n0 + r0 + i < NODES) {
                float4 o;
                upk(a2[i][0], o.x, o.y); upk(a2[i][1], o.z, o.w);
                o.x *= scale; o.y *= scale; o.z *= scale; o.w *= scale;
                *(float4*)(g_qkt + (size_t)(n0 + r0 + i) * 512 + h * 128 + c0) = o;
            }
        }
    }
}

// ---------------------------------------------------------------------------
// K2: attention core. One warp per node. Only rows s < L are read from HBM.
// mask_idx==0: reference's -1e9 on ALL positions annihilates score
// differences in fp32 -> softmax is exactly uniform 1/32. Skip key reads.
// ---------------------------------------------------------------------------
__global__ __launch_bounds__(256) void k2_kernel(
    const float* __restrict__ key, const float* __restrict__ value,
    const int* __restrict__ mask_idx)
{
    __shared__ float  sqk[8][4][128];
    __shared__ float4 sattn[8][32];

    const int w = threadIdx.x >> 5, l = threadIdx.x & 31;
    const int n = blockIdx.x * 8 + w;

    const int mi = mask_idx[n];
    const int L = (mi == 0) ? 32 : mi;

    if (mi == 0) {
        const float ua = 1.0f / 32.0f;
        sattn[w][l] = make_float4(ua, ua, ua, ua);
    } else {
        {
            const float4* qsrc = (const float4*)(g_qkt + (size_t)n * 512);
#pragma unroll
            for (int h = 0; h < 4; h++)
                *(float4*)&sqk[w][h][4 * l] = qsrc[h * 32 + l];
        }
        __syncwarp();

        float sc[4] = {-INFINITY, -INFINITY, -INFINITY, -INFINITY};
        if (l < L) {
            const float4* krow = (const float4*)(key + ((size_t)l * NODES + n) * 128);
            float s0 = 0.f, s1 = 0.f, s2 = 0.f, s3 = 0.f;
#pragma unroll 4
            for (int c = 0; c < 32; c++) {
                float4 kv = krow[c];
                float4 q0 = *(const float4*)&sqk[w][0][4 * c];
                float4 q1 = *(const float4*)&sqk[w][1][4 * c];
                float4 q2 = *(const float4*)&sqk[w][2][4 * c];
                float4 q3 = *(const float4*)&sqk[w][3][4 * c];
                s0 = fmaf(kv.x, q0.x, fmaf(kv.y, q0.y, fmaf(kv.z, q0.z, fmaf(kv.w, q0.w, s0))));
                s1 = fmaf(kv.x, q1.x, fmaf(kv.y, q1.y, fmaf(kv.z, q1.z, fmaf(kv.w, q1.w, s1))));
                s2 = fmaf(kv.x, q2.x, fmaf(kv.y, q2.y, fmaf(kv.z, q2.z, fmaf(kv.w, q2.w, s2))));
                s3 = fmaf(kv.x, q3.x, fmaf(kv.y, q3.y, fmaf(kv.z, q3.z, fmaf(kv.w, q3.w, s3))));
            }
            sc[0] = s0; sc[1] = s1; sc[2] = s2; sc[3] = s3;
        }

        float at[4];
#pragma unroll
        for (int h = 0; h < 4; h++) {
            float m = sc[h];
#pragma unroll
            for (int off = 16; off; off >>= 1)
                m = fmaxf(m, __shfl_xor_sync(0xffffffffu, m, off));
            float e = __expf(sc[h] - m);
            float ssum = e;
#pragma unroll
            for (int off = 16; off; off >>= 1)
                ssum += __shfl_xor_sync(0xffffffffu, ssum, off);
            at[h] = e / ssum;
        }
        sattn[w][l] = make_float4(at[0], at[1], at[2], at[3]);
    }
    __syncwarp();

    float u0[4] = {0,0,0,0}, u1[4] = {0,0,0,0}, u2[4] = {0,0,0,0}, u3[4] = {0,0,0,0};
    const float* vbase = value + (size_t)n * 128 + 4 * l;
    int s = 0;
    for (; s + 2 <= L; s += 2) {
        float4 a  = sattn[w][s];
        float4 a2 = sattn[w][s + 1];
        float4 v  = *(const float4*)(vbase + (size_t)s * (NODES * 128));
        float4 v2 = *(const float4*)(vbase + (size_t)(s + 1) * (NODES * 128));
        float vv[4]  = {v.x, v.y, v.z, v.w};
        float vv2[4] = {v2.x, v2.y, v2.z, v2.w};
#pragma unroll
        for (int j = 0; j < 4; j++) {
            u0[j] = fmaf(a.x, vv[j], u0[j]);  u0[j] = fmaf(a2.x, vv2[j], u0[j]);
            u1[j] = fmaf(a.y, vv[j], u1[j]);  u1[j] = fmaf(a2.y, vv2[j], u1[j]);
            u2[j] = fmaf(a.z, vv[j], u2[j]);  u2[j] = fmaf(a2.z, vv2[j], u2[j]);
            u3[j] = fmaf(a.w, vv[j], u3[j]);  u3[j] = fmaf(a2.w, vv2[j], u3[j]);
        }
    }
    if (s < L) {
        float4 a = sattn[w][s];
        float4 v = *(const float4*)(vbase + (size_t)s * (NODES * 128));
        float vv[4] = {v.x, v.y, v.z, v.w};
#pragma unroll
        for (int j = 0; j < 4; j++) {
            u0[j] = fmaf(a.x, vv[j], u0[j]);
            u1[j] = fmaf(a.y, vv[j], u1[j]);
            u2[j] = fmaf(a.z, vv[j], u2[j]);
            u3[j] = fmaf(a.w, vv[j], u3[j]);
        }
    }
    float* ub = g_u + (size_t)n * 512 + 4 * l;
    *(float4*)(ub +   0) = make_float4(u0[0], u0[1], u0[2], u0[3]);
    *(float4*)(ub + 128) = make_float4(u1[0], u1[1], u1[2], u1[3]);
    *(float4*)(ub + 256) = make_float4(u2[0], u2[1], u2[2], u2[3]);
    *(float4*)(ub + 384) = make_float4(u3[0], u3[1], u3[2], u3[3]);
}

// ---------------------------------------------------------------------------
// K3: out = u @ W2 + b2;  LN;  + query.   (W2 = blockdiag(Wv)@Wo precomputed)
// 64 nodes/CTA, warp-private 8 rows, A staged in smem per 128-k chunk.
// NO __syncthreads. B via LDG (coalesced rows, L1-hot).
// ---------------------------------------------------------------------------
__global__ __launch_bounds__(256, 3) void k3_kernel(
    const float* __restrict__ gamma, const float* __restrict__ beta,
    const float* __restrict__ query, float* __restrict__ out)
{
    __shared__ float bufA[64 * 132];

    const int t = threadIdx.x;
    const int n0 = blockIdx.x * 64;
    const int lane = t & 31, wg = t >> 5;
    const int c0 = 4 * lane, r0 = 8 * wg;
    float* myA = bufA + r0 * 132;   // warp-private 8 rows

    ull acc[8][2];
#pragma unroll
    for (int i = 0; i < 8; i++) { acc[i][0] = 0ull; acc[i][1] = 0ull; }

    for (int ch = 0; ch < 4; ch++) {
        // stage this warp's 8 u-rows (current 128-k chunk) into smem, coalesced
#pragma unroll
        for (int i = 0; i < 8; i++) {
            const int row = n0 + r0 + i;
            float4 v = (row < NODES)
                ? *(const float4*)(g_u + (size_t)row * 512 + ch * 128 + c0)
                : make_float4(0.f, 0.f, 0.f, 0.f);
            *(float4*)(myA + i * 132 + c0) = v;
        }
        __syncwarp();
        const float* B = g_w2 + ch * 128 * 128;
#pragma unroll 4
        for (int k = 0; k < 128; k += 4) {
            GEMM_STEP_LDGB(myA, k, B, k, c0, acc);
        }
        __syncwarp();   // reads done before next chunk overwrites
    }

    float4 b24 = *(const float4*)(g_b2 + c0);
    float4 g4  = *(const float4*)(gamma + c0);
    float4 be4 = *(const float4*)(beta + c0);

#pragma unroll
    for (int i = 0; i < 8; i++) {
        float o[4];
        upk(acc[i][0], o[0], o[1]); upk(acc[i][1], o[2], o[3]);
        o[0] += b24.x; o[1] += b24.y; o[2] += b24.z; o[3] += b24.w;
        float s  = o[0] + o[1] + o[2] + o[3];
        float sq = o[0]*o[0] + o[1]*o[1] + o[2]*o[2] + o[3]*o[3];
#pragma unroll
        for (int off = 16; off; off >>= 1) {
            s  += __shfl_xor_sync(0xffffffffu, s, off);
            sq += __shfl_xor_sync(0xffffffffu, sq, off);
        }
        const int row = n0 + r0 + i;
        if (row < NODES) {
            float mu = s * (1.f / 128.f);
            float var = sq * (1.f / 128.f) - mu * mu;
            float rstd = rsqrtf(var + 1e-5f);
            float4 q4 = *(const float4*)(query + (size_t)row * 128 + c0);
            float4 res;
            res.x = q4.x + (o[0] - mu) * rstd * g4.x + be4.x;
            res.y = q4.y + (o[1] - mu) * rstd * g4.y + be4.y;
            res.z = q4.z + (o[2] - mu) * rstd * g4.z + be4.z;
            res.w = q4.w + (o[3] - mu) * rstd * g4.w + be4.w;
            *(float4*)(out + (size_t)row * 128 + c0) = res;
        }
    }
}

extern "C" void kernel_launch(void* const* d_in, const int* in_sizes, int n_in,
                              void* d_out, int out_size) {
    const float* query = (const float*)d_in[0];
    const float* key   = (const float*)d_in[1];
    const float* value = (const float*)d_in[2];
    const int*   midx  = (const int*)d_in[3];
    const float* Wq = (const float*)d_in[4];
    const float* bq = (const float*)d_in[5];
    const float* Wk = (const float*)d_in[6];
    // bk = d_in[7] cancels in softmax (and is zero) — unused
    const float* Wv = (const float*)d_in[8];
    const float* bv = (const float*)d_in[9];
    const float* Wo = (const float*)d_in[10];
    const float* bo = (const float*)d_in[11];
    const float* gamma = (const float*)d_in[12];
    const float* beta  = (const float*)d_in[13];
    float* out = (float*)d_out;

    const int grid14 = (NODES + 63) / 64;  // 313
    k0_transpose<<<16, 256>>>(Wk);
    k0b_fuse<<<256, 256>>>(Wv, Wo, bv, bo);
    k1_kernel<<<grid14, 256>>>(query, Wq, bq);
    k2_kernel<<<NODES / 8, 256>>>(key, value, midx);
    k3_kernel<<<grid14, 256>>>(gamma, beta, query, out);
}